// round 2
// baseline (speedup 1.0000x reference)
#include <cuda_runtime.h>
#include <cstdint>

#define B_ 4
#define CX 512
#define CY 256
#define M_ 64
#define N_ 4096
#define EPS_ 1e-5f
#define TOT_ 16384.0f  // B_*N_

// ---------------- device scratch (no allocations allowed) ----------------
__device__ __align__(16) float g_z1[3 * B_ * M_ * N_];   // stage-1 conv outputs [p][b][m][n]
__device__ __align__(16) float g_z2[3 * B_ * M_ * N_];   // stage-2 conv outputs (pre-BN2)
__device__ __align__(16) float g_fout[B_ * M_ * N_];     // attention output [b][m][n]
__device__ float g_a1[192], g_bf1[192];                  // BN1 folded affine per channel
__device__ __align__(16) float g_w2eff[3 * 64 * 64];     // stage-2 weights with BN1 folded
__device__ float g_c2[192];                              // stage-2 bias from BN1 fold
__device__ float g_a2[192], g_bf2[192];                  // BN2 affine (normalized = a*z + bf)
__device__ float g_meanf[64];                            // raw channel sums of fout
__device__ float g_gram[64 * 64];                        // fout gram (atomic accum)
__device__ float g_au[512], g_bu[512];                   // final BN affine

// ---------------- zero the atomic accumulators ----------------
__global__ void k_zero() {
    int t = threadIdx.x;
    for (int i = t; i < 4096; i += 256) g_gram[i] = 0.f;
}

// ---------------- stage-1 conv1x1: z1[p][b] = W_p @ X_b ----------------
// tile 64 rows x 128 cols, 256 threads, micro 8x4
__global__ __launch_bounds__(256) void k_gemm1(
    const float* __restrict__ x, const float* __restrict__ y,
    const float* __restrict__ ws1, const float* __restrict__ wx1, const float* __restrict__ wy1)
{
    __shared__ float Ws[16 * 68];
    __shared__ float Xs[16 * 132];
    int p = blockIdx.z, b = blockIdx.y, n0 = blockIdx.x * 128;
    const float* W = (p == 0) ? ws1 : (p == 1) ? wx1 : wy1;
    const float* X = (p == 2) ? (y + (size_t)b * CY * N_) : (x + (size_t)b * CX * N_);
    int K = (p == 2) ? CY : CX;
    float* C = g_z1 + ((size_t)(p * B_ + b) * M_) * N_ + n0;
    int tid = threadIdx.x;
    int ty = tid >> 5, tx = tid & 31;
    float acc[8][4];
#pragma unroll
    for (int r = 0; r < 8; ++r) { acc[r][0] = acc[r][1] = acc[r][2] = acc[r][3] = 0.f; }

    for (int k0 = 0; k0 < K; k0 += 16) {
        {
            int m = tid >> 2, kq = tid & 3;
            float4 w4 = *(const float4*)(W + (size_t)m * K + k0 + 4 * kq);
            Ws[(4 * kq + 0) * 68 + m] = w4.x; Ws[(4 * kq + 1) * 68 + m] = w4.y;
            Ws[(4 * kq + 2) * 68 + m] = w4.z; Ws[(4 * kq + 3) * 68 + m] = w4.w;
        }
#pragma unroll
        for (int it = 0; it < 2; ++it) {
            int idx = it * 256 + tid;
            int k = idx >> 5, nq = idx & 31;
            *(float4*)(Xs + k * 132 + 4 * nq) =
                *(const float4*)(X + (size_t)(k0 + k) * N_ + n0 + 4 * nq);
        }
        __syncthreads();
#pragma unroll
        for (int d = 0; d < 16; ++d) {
            float4 a0 = *(const float4*)(Ws + d * 68 + 8 * ty);
            float4 a1 = *(const float4*)(Ws + d * 68 + 8 * ty + 4);
            float4 bb = *(const float4*)(Xs + d * 132 + 4 * tx);
            float av[8] = {a0.x, a0.y, a0.z, a0.w, a1.x, a1.y, a1.z, a1.w};
#pragma unroll
            for (int r = 0; r < 8; ++r) {
                acc[r][0] += av[r] * bb.x; acc[r][1] += av[r] * bb.y;
                acc[r][2] += av[r] * bb.z; acc[r][3] += av[r] * bb.w;
            }
        }
        __syncthreads();
    }
#pragma unroll
    for (int r = 0; r < 8; ++r) {
        *(float4*)(C + (size_t)(8 * ty + r) * N_ + 4 * tx) =
            make_float4(acc[r][0], acc[r][1], acc[r][2], acc[r][3]);
    }
}

// ---------------- per-channel batch stats -> folded BN affine ----------------
__global__ void k_stats(int which,
                        const float* __restrict__ gs, const float* __restrict__ bs,
                        const float* __restrict__ gx, const float* __restrict__ bx,
                        const float* __restrict__ gy, const float* __restrict__ by)
{
    __shared__ float s1[256], s2[256];
    const float* Z = (which == 0) ? g_z1 : g_z2;
    float* ao = (which == 0) ? g_a1 : g_a2;
    float* bo = (which == 0) ? g_bf1 : g_bf2;
    int ch = blockIdx.x, p = ch >> 6, m = ch & 63;
    int tid = threadIdx.x;
    float sum = 0.f, sq = 0.f;
    const float* base = Z + ((size_t)(p * B_) * M_ + m) * N_;
    for (int b = 0; b < B_; ++b) {
        const float* row = base + (size_t)b * M_ * N_;
        for (int i = tid; i < N_; i += 256) { float v = row[i]; sum += v; sq += v * v; }
    }
    s1[tid] = sum; s2[tid] = sq; __syncthreads();
    for (int off = 128; off; off >>= 1) {
        if (tid < off) { s1[tid] += s1[tid + off]; s2[tid] += s2[tid + off]; }
        __syncthreads();
    }
    if (tid == 0) {
        float mean = s1[0] / TOT_;
        float var = s2[0] / TOT_ - mean * mean;
        const float* g = (p == 0) ? gs : (p == 1) ? gx : gy;
        const float* bb = (p == 0) ? bs : (p == 1) ? bx : by;
        float a = g[m] * rsqrtf(var + EPS_);
        ao[ch] = a;
        bo[ch] = bb[m] - a * mean;
    }
}

// ---------------- fold BN1 into stage-2 weights ----------------
__global__ void k_foldw2(const float* __restrict__ ws2, const float* __restrict__ wx2,
                         const float* __restrict__ wy2)
{
    int p = blockIdx.x, tid = threadIdx.x;
    const float* w2 = (p == 0) ? ws2 : (p == 1) ? wx2 : wy2;
    for (int idx = tid; idx < 4096; idx += 256) {
        int k = idx & 63;
        g_w2eff[p * 4096 + idx] = w2[idx] * g_a1[p * 64 + k];
    }
    if (tid < 64) {
        float s = 0.f;
        for (int k = 0; k < 64; ++k) s += w2[tid * 64 + k] * g_bf1[p * 64 + k];
        g_c2[p * 64 + tid] = s;
    }
}

// ---------------- stage-2 conv1x1 (K=64) ----------------
__global__ __launch_bounds__(256) void k_gemm2()
{
    __shared__ float Ws[16 * 68];
    __shared__ float Xs[16 * 132];
    int z = blockIdx.y, p = z >> 2;
    int n0 = blockIdx.x * 128;
    const float* W = g_w2eff + p * 4096;
    const float* X = g_z1 + (size_t)z * M_ * N_;
    float* C = g_z2 + (size_t)z * M_ * N_ + n0;
    int tid = threadIdx.x;
    int ty = tid >> 5, tx = tid & 31;
    float acc[8][4];
#pragma unroll
    for (int r = 0; r < 8; ++r) { acc[r][0] = acc[r][1] = acc[r][2] = acc[r][3] = 0.f; }

    for (int k0 = 0; k0 < 64; k0 += 16) {
        {
            int m = tid >> 2, kq = tid & 3;
            float4 w4 = *(const float4*)(W + (size_t)m * 64 + k0 + 4 * kq);
            Ws[(4 * kq + 0) * 68 + m] = w4.x; Ws[(4 * kq + 1) * 68 + m] = w4.y;
            Ws[(4 * kq + 2) * 68 + m] = w4.z; Ws[(4 * kq + 3) * 68 + m] = w4.w;
        }
#pragma unroll
        for (int it = 0; it < 2; ++it) {
            int idx = it * 256 + tid;
            int k = idx >> 5, nq = idx & 31;
            *(float4*)(Xs + k * 132 + 4 * nq) =
                *(const float4*)(X + (size_t)(k0 + k) * N_ + n0 + 4 * nq);
        }
        __syncthreads();
#pragma unroll
        for (int d = 0; d < 16; ++d) {
            float4 a0 = *(const float4*)(Ws + d * 68 + 8 * ty);
            float4 a1 = *(const float4*)(Ws + d * 68 + 8 * ty + 4);
            float4 bb = *(const float4*)(Xs + d * 132 + 4 * tx);
            float av[8] = {a0.x, a0.y, a0.z, a0.w, a1.x, a1.y, a1.z, a1.w};
#pragma unroll
            for (int r = 0; r < 8; ++r) {
                acc[r][0] += av[r] * bb.x; acc[r][1] += av[r] * bb.y;
                acc[r][2] += av[r] * bb.z; acc[r][3] += av[r] * bb.w;
            }
        }
        __syncthreads();
    }
#pragma unroll
    for (int r = 0; r < 8; ++r) {
        float bias = g_c2[p * 64 + 8 * ty + r];
        *(float4*)(C + (size_t)(8 * ty + r) * N_ + 4 * tx) =
            make_float4(acc[r][0] + bias, acc[r][1] + bias, acc[r][2] + bias, acc[r][3] + bias);
    }
}

// ---------------- fused flash attention: 128 queries/block, 64-key tiles ----------------
// Qs [64m][132] transposed, Ks [64m][68], Ps [128i][68], Vs [64j][65] transposed.
__global__ __launch_bounds__(256) void k_attn()
{
    extern __shared__ float sm[];
    float* Qs = sm;                   // 64*132
    float* Ks = Qs + 64 * 132;        // 64*68
    float* Ps = Ks + 64 * 68;         // 128*68
    float* Vs = Ps + 128 * 68;        // 64*65
    int b = blockIdx.y;
    int q0 = blockIdx.x * 128;
    int tid = threadIdx.x;
    int ty = tid >> 4, tx = tid & 15;   // rows 8*ty.., cols 4*tx..

    const float* zq = g_z2 + ((size_t)(1 * B_ + b) * M_) * N_;  // f_x  (queries)
    const float* zk = g_z2 + ((size_t)(2 * B_ + b) * M_) * N_;  // f_y  (keys)
    const float* zv = g_z2 + ((size_t)(0 * B_ + b) * M_) * N_;  // f_self (values)

    // load Q tile (128 rows x 64 m), BN2 applied, stored transposed Qs[m][i]
#pragma unroll
    for (int it = 0; it < 8; ++it) {
        int idx = it * 256 + tid;
        int m = idx >> 5, iq = idx & 31;
        float a = g_a2[64 + m], bet = g_bf2[64 + m];
        float4 v = *(const float4*)(zq + (size_t)m * N_ + q0 + 4 * iq);
        *(float4*)(Qs + m * 132 + 4 * iq) =
            make_float4(a * v.x + bet, a * v.y + bet, a * v.z + bet, a * v.w + bet);
    }

    float O[8][4];
    float mrow[8], lrow[8];
    const float NEG_INF = __int_as_float(0xff800000);
#pragma unroll
    for (int r = 0; r < 8; ++r) {
        O[r][0] = O[r][1] = O[r][2] = O[r][3] = 0.f;
        mrow[r] = NEG_INF; lrow[r] = 0.f;
    }

    for (int j0 = 0; j0 < N_; j0 += 64) {
        __syncthreads();  // protect Ks/Vs from previous PV; makes Qs visible on first iter
        // K tile: Ks[m][j], BN2 applied
#pragma unroll
        for (int it = 0; it < 4; ++it) {
            int idx = it * 256 + tid;
            int m = idx >> 4, jq = idx & 15;
            float a = g_a2[128 + m], bet = g_bf2[128 + m];
            float4 v = *(const float4*)(zk + (size_t)m * N_ + j0 + 4 * jq);
            *(float4*)(Ks + m * 68 + 4 * jq) =
                make_float4(a * v.x + bet, a * v.y + bet, a * v.z + bet, a * v.w + bet);
        }
        // V tile: transposed store Vs[j][c], BN2 applied
#pragma unroll
        for (int it = 0; it < 4; ++it) {
            int idx = it * 256 + tid;
            int c = idx >> 4, jq = idx & 15;
            float a = g_a2[c], bet = g_bf2[c];
            float4 v = *(const float4*)(zv + (size_t)c * N_ + j0 + 4 * jq);
            Vs[(4 * jq + 0) * 65 + c] = a * v.x + bet;
            Vs[(4 * jq + 1) * 65 + c] = a * v.y + bet;
            Vs[(4 * jq + 2) * 65 + c] = a * v.z + bet;
            Vs[(4 * jq + 3) * 65 + c] = a * v.w + bet;
        }
        __syncthreads();

        // S = Q @ K  (contraction over m)
        float s[8][4];
#pragma unroll
        for (int r = 0; r < 8; ++r) { s[r][0] = s[r][1] = s[r][2] = s[r][3] = 0.f; }
#pragma unroll 8
        for (int d = 0; d < 64; ++d) {
            float4 a0 = *(const float4*)(Qs + d * 132 + 8 * ty);
            float4 a1 = *(const float4*)(Qs + d * 132 + 8 * ty + 4);
            float4 bb = *(const float4*)(Ks + d * 68 + 4 * tx);
            float av[8] = {a0.x, a0.y, a0.z, a0.w, a1.x, a1.y, a1.z, a1.w};
#pragma unroll
            for (int r = 0; r < 8; ++r) {
                s[r][0] += av[r] * bb.x; s[r][1] += av[r] * bb.y;
                s[r][2] += av[r] * bb.z; s[r][3] += av[r] * bb.w;
            }
        }

        // online softmax (row groups of 16 threads; xor-shuffles stay in 16-lane half)
#pragma unroll
        for (int r = 0; r < 8; ++r) {
            float rm = fmaxf(fmaxf(s[r][0], s[r][1]), fmaxf(s[r][2], s[r][3]));
            rm = fmaxf(rm, __shfl_xor_sync(0xffffffffu, rm, 1));
            rm = fmaxf(rm, __shfl_xor_sync(0xffffffffu, rm, 2));
            rm = fmaxf(rm, __shfl_xor_sync(0xffffffffu, rm, 4));
            rm = fmaxf(rm, __shfl_xor_sync(0xffffffffu, rm, 8));
            float mnew = fmaxf(mrow[r], rm);
            float corr = __expf(mrow[r] - mnew);
            mrow[r] = mnew;
            float ps = 0.f;
#pragma unroll
            for (int c = 0; c < 4; ++c) {
                float e = __expf(s[r][c] - mnew);
                s[r][c] = e; ps += e;
            }
            ps += __shfl_xor_sync(0xffffffffu, ps, 1);
            ps += __shfl_xor_sync(0xffffffffu, ps, 2);
            ps += __shfl_xor_sync(0xffffffffu, ps, 4);
            ps += __shfl_xor_sync(0xffffffffu, ps, 8);
            lrow[r] = lrow[r] * corr + ps;
            O[r][0] *= corr; O[r][1] *= corr; O[r][2] *= corr; O[r][3] *= corr;
            *(float4*)(Ps + (8 * ty + r) * 68 + 4 * tx) =
                make_float4(s[r][0], s[r][1], s[r][2], s[r][3]);
        }
        __syncthreads();

        // O += P @ V  (contraction over j)
#pragma unroll 8
        for (int d = 0; d < 64; ++d) {
            float b0 = Vs[d * 65 + 4 * tx + 0];
            float b1 = Vs[d * 65 + 4 * tx + 1];
            float b2 = Vs[d * 65 + 4 * tx + 2];
            float b3 = Vs[d * 65 + 4 * tx + 3];
#pragma unroll
            for (int r = 0; r < 8; ++r) {
                float a = Ps[(8 * ty + r) * 68 + d];
                O[r][0] += a * b0; O[r][1] += a * b1;
                O[r][2] += a * b2; O[r][3] += a * b3;
            }
        }
    }

    // normalize + store transposed into g_fout[b][c][n]
#pragma unroll
    for (int r = 0; r < 8; ++r) {
        float inv = 1.f / lrow[r];
        int n = q0 + 8 * ty + r;
#pragma unroll
        for (int c = 0; c < 4; ++c) {
            g_fout[((size_t)b * M_ + 4 * tx + c) * N_ + n] = O[r][c] * inv;
        }
    }
}

// ---------------- gram of fout (for exact final-BN variance) ----------------
__global__ __launch_bounds__(256) void k_gram()
{
    __shared__ float Fs[64 * 129];
    int chunk = blockIdx.x;
    int b = chunk >> 2, nbase = (chunk & 3) * 1024;
    int tid = threadIdx.x;
    int ty = tid >> 4, tx = tid & 15;  // m1 = 4*ty.., m2 = 4*tx..
    float acc[4][4];
#pragma unroll
    for (int r = 0; r < 4; ++r) { acc[r][0] = acc[r][1] = acc[r][2] = acc[r][3] = 0.f; }

    for (int sub = 0; sub < 8; ++sub) {
        int n0 = nbase + sub * 128;
        __syncthreads();
#pragma unroll
        for (int it = 0; it < 8; ++it) {
            int idx = it * 256 + tid;
            int m = idx >> 5, nq = idx & 31;
            float4 v = *(const float4*)(g_fout + ((size_t)b * M_ + m) * N_ + n0 + 4 * nq);
            Fs[m * 129 + 4 * nq + 0] = v.x; Fs[m * 129 + 4 * nq + 1] = v.y;
            Fs[m * 129 + 4 * nq + 2] = v.z; Fs[m * 129 + 4 * nq + 3] = v.w;
        }
        __syncthreads();
        for (int d = 0; d < 128; ++d) {
            float a0 = Fs[(4 * ty + 0) * 129 + d];
            float a1 = Fs[(4 * ty + 1) * 129 + d];
            float a2 = Fs[(4 * ty + 2) * 129 + d];
            float a3 = Fs[(4 * ty + 3) * 129 + d];
            float b0 = Fs[(4 * tx + 0) * 129 + d];
            float b1 = Fs[(4 * tx + 1) * 129 + d];
            float b2 = Fs[(4 * tx + 2) * 129 + d];
            float b3 = Fs[(4 * tx + 3) * 129 + d];
            acc[0][0] += a0 * b0; acc[0][1] += a0 * b1; acc[0][2] += a0 * b2; acc[0][3] += a0 * b3;
            acc[1][0] += a1 * b0; acc[1][1] += a1 * b1; acc[1][2] += a1 * b2; acc[1][3] += a1 * b3;
            acc[2][0] += a2 * b0; acc[2][1] += a2 * b1; acc[2][2] += a2 * b2; acc[2][3] += a2 * b3;
            acc[3][0] += a3 * b0; acc[3][1] += a3 * b1; acc[3][2] += a3 * b2; acc[3][3] += a3 * b3;
        }
    }
#pragma unroll
    for (int r = 0; r < 4; ++r)
#pragma unroll
        for (int c = 0; c < 4; ++c)
            atomicAdd(&g_gram[(4 * ty + r) * 64 + 4 * tx + c], acc[r][c]);
}

// ---------------- channel sums of fout ----------------
__global__ void k_meanf()
{
    __shared__ float s1[256];
    int m = blockIdx.x, tid = threadIdx.x;
    float sum = 0.f;
    for (int b = 0; b < B_; ++b) {
        const float* row = g_fout + ((size_t)b * M_ + m) * N_;
        for (int i = tid; i < N_; i += 256) sum += row[i];
    }
    s1[tid] = sum; __syncthreads();
    for (int off = 128; off; off >>= 1) {
        if (tid < off) s1[tid] += s1[tid + off];
        __syncthreads();
    }
    if (tid == 0) g_meanf[m] = s1[0];
}

// ---------------- final BN affine via gram: var(u_c)=wGw/T - mean^2 ----------------
__global__ void k_bnup(const float* __restrict__ wu, const float* __restrict__ gu,
                       const float* __restrict__ bu)
{
    __shared__ float s1[64], s2[64];
    int c = blockIdx.x, t = threadIdx.x;
    float tmp = 0.f;
    for (int k = 0; k < 64; ++k) tmp += g_gram[t * 64 + k] * wu[c * 64 + k];
    float wt = wu[c * 64 + t];
    s1[t] = wt * tmp;
    s2[t] = wt * g_meanf[t];
    __syncthreads();
    for (int off = 32; off; off >>= 1) {
        if (t < off) { s1[t] += s1[t + off]; s2[t] += s2[t + off]; }
        __syncthreads();
    }
    if (t == 0) {
        float mean = s2[0] / TOT_;
        float eu2 = s1[0] / TOT_;
        float var = eu2 - mean * mean;
        float a = gu[c] * rsqrtf(var + EPS_);
        g_au[c] = a;
        g_bu[c] = bu[c] - a * mean;
    }
}

// ---------------- final: out = x + BN(wu @ fout) ----------------
__global__ __launch_bounds__(256) void k_final(const float* __restrict__ x,
                                               const float* __restrict__ wu,
                                               float* __restrict__ out)
{
    __shared__ float Ws[16 * 68];
    __shared__ float Xs[16 * 132];
    int n0 = blockIdx.x * 128, c0 = blockIdx.y * 64, b = blockIdx.z;
    const float* F = g_fout + (size_t)b * M_ * N_;
    int tid = threadIdx.x;
    int ty = tid >> 5, tx = tid & 31;
    float acc[8][4];
#pragma unroll
    for (int r = 0; r < 8; ++r) { acc[r][0] = acc[r][1] = acc[r][2] = acc[r][3] = 0.f; }

    for (int k0 = 0; k0 < 64; k0 += 16) {
        {
            int m = tid >> 2, kq = tid & 3;
            float4 w4 = *(const float4*)(wu + (size_t)(c0 + m) * 64 + k0 + 4 * kq);
            Ws[(4 * kq + 0) * 68 + m] = w4.x; Ws[(4 * kq + 1) * 68 + m] = w4.y;
            Ws[(4 * kq + 2) * 68 + m] = w4.z; Ws[(4 * kq + 3) * 68 + m] = w4.w;
        }
#pragma unroll
        for (int it = 0; it < 2; ++it) {
            int idx = it * 256 + tid;
            int k = idx >> 5, nq = idx & 31;
            *(float4*)(Xs + k * 132 + 4 * nq) =
                *(const float4*)(F + (size_t)(k0 + k) * N_ + n0 + 4 * nq);
        }
        __syncthreads();
#pragma unroll
        for (int d = 0; d < 16; ++d) {
            float4 a0 = *(const float4*)(Ws + d * 68 + 8 * ty);
            float4 a1 = *(const float4*)(Ws + d * 68 + 8 * ty + 4);
            float4 bb = *(const float4*)(Xs + d * 132 + 4 * tx);
            float av[8] = {a0.x, a0.y, a0.z, a0.w, a1.x, a1.y, a1.z, a1.w};
#pragma unroll
            for (int r = 0; r < 8; ++r) {
                acc[r][0] += av[r] * bb.x; acc[r][1] += av[r] * bb.y;
                acc[r][2] += av[r] * bb.z; acc[r][3] += av[r] * bb.w;
            }
        }
        __syncthreads();
    }
#pragma unroll
    for (int r = 0; r < 8; ++r) {
        int c = c0 + 8 * ty + r;
        float a = g_au[c], bet = g_bu[c];
        size_t o = ((size_t)b * CX + c) * N_ + n0 + 4 * tx;
        float4 xv = *(const float4*)(x + o);
        *(float4*)(out + o) = make_float4(
            xv.x + a * acc[r][0] + bet, xv.y + a * acc[r][1] + bet,
            xv.z + a * acc[r][2] + bet, xv.w + a * acc[r][3] + bet);
    }
}

#define ATTN_SMEM ((64 * 132 + 64 * 68 + 128 * 68 + 64 * 65) * 4)

extern "C" void kernel_launch(void* const* d_in, const int* in_sizes, int n_in,
                              void* d_out, int out_size)
{
    const float* x   = (const float*)d_in[0];
    const float* y   = (const float*)d_in[1];
    const float* ws1 = (const float*)d_in[2];
    const float* gs1 = (const float*)d_in[3];
    const float* bs1 = (const float*)d_in[4];
    const float* ws2 = (const float*)d_in[5];
    const float* gs2 = (const float*)d_in[6];
    const float* bs2 = (const float*)d_in[7];
    const float* wx1 = (const float*)d_in[8];
    const float* gx1 = (const float*)d_in[9];
    const float* bx1 = (const float*)d_in[10];
    const float* wx2 = (const float*)d_in[11];
    const float* gx2 = (const float*)d_in[12];
    const float* bx2 = (const float*)d_in[13];
    const float* wy1 = (const float*)d_in[14];
    const float* gy1 = (const float*)d_in[15];
    const float* by1 = (const float*)d_in[16];
    const float* wy2 = (const float*)d_in[17];
    const float* gy2 = (const float*)d_in[18];
    const float* by2 = (const float*)d_in[19];
    const float* wu  = (const float*)d_in[20];
    const float* gu  = (const float*)d_in[21];
    const float* bu  = (const float*)d_in[22];
    float* out = (float*)d_out;

    cudaFuncSetAttribute(k_attn, cudaFuncAttributeMaxDynamicSharedMemorySize, ATTN_SMEM);

    k_zero<<<1, 256>>>();
    k_gemm1<<<dim3(32, B_, 3), 256>>>(x, y, ws1, wx1, wy1);
    k_stats<<<192, 256>>>(0, gs1, bs1, gx1, bx1, gy1, by1);
    k_foldw2<<<3, 256>>>(ws2, wx2, wy2);
    k_gemm2<<<dim3(32, 12), 256>>>();
    k_stats<<<192, 256>>>(1, gs2, bs2, gx2, bx2, gy2, by2);
    k_attn<<<dim3(32, B_), 256, ATTN_SMEM>>>();
    k_gram<<<16, 256>>>();
    k_meanf<<<64, 256>>>();
    k_bnup<<<512, 64>>>(wu, gu, bu);
    k_final<<<dim3(32, 8, B_), 256>>>(x, wu, out);
}

// round 3
// speedup vs baseline: 1.0746x; 1.0746x over previous
#include <cuda_runtime.h>
#include <cstdint>

#define B_ 4
#define CX 512
#define CY 256
#define M_ 64
#define N_ 4096
#define EPS_ 1e-5f
#define TOT_ 16384.0f  // B_*N_

typedef unsigned long long u64;

// ---- packed f32x2 helpers (sm_103a FFMA2 path; PTX-only) ----
__device__ __forceinline__ u64 d2(float v) {
    u64 r; asm("mov.b64 %0,{%1,%1};" : "=l"(r) : "f"(v)); return r;
}
__device__ __forceinline__ void up2(u64 v, float& a, float& b) {
    asm("mov.b64 {%0,%1},%2;" : "=f"(a), "=f"(b) : "l"(v));
}
__device__ __forceinline__ void fma2(u64& d, u64 a, u64 b) {
    asm("fma.rn.f32x2 %0,%1,%2,%0;" : "+l"(d) : "l"(a), "l"(b));
}
__device__ __forceinline__ void mul2(u64& d, u64 a) {
    asm("mul.rn.f32x2 %0,%0,%1;" : "+l"(d) : "l"(a));
}

// ---------------- device scratch (no allocations allowed) ----------------
__device__ __align__(16) float g_z1[3 * B_ * M_ * N_];   // stage-1 conv outputs [p][b][m][n]
__device__ __align__(16) float g_z2[3 * B_ * M_ * N_];   // stage-2 conv outputs (pre-BN2)
__device__ __align__(16) float g_fout[B_ * M_ * N_];     // attention output [b][m][n]
__device__ float g_a1[192], g_bf1[192];                  // BN1 folded affine per channel
__device__ __align__(16) float g_w2eff[3 * 64 * 64];     // stage-2 weights with BN1 folded
__device__ float g_c2[192];                              // stage-2 bias from BN1 fold
__device__ float g_a2[192], g_bf2[192];                  // BN2 affine (normalized = a*z + bf)
__device__ float g_meanf[64];                            // raw channel sums of fout
__device__ float g_gram[64 * 64];                        // fout gram (atomic accum)
__device__ float g_au[512], g_bu[512];                   // final BN affine

__global__ void k_zero() {
    int t = threadIdx.x;
    for (int i = t; i < 4096; i += 256) g_gram[i] = 0.f;
}

// ---------------- stage-1 conv1x1: z1[p][b] = W_p @ X_b ----------------
// tile 64 rows x 128 cols, 256 threads, micro 8x4 (row-pair packed f32x2)
__global__ __launch_bounds__(256) void k_gemm1(
    const float* __restrict__ x, const float* __restrict__ y,
    const float* __restrict__ ws1, const float* __restrict__ wx1, const float* __restrict__ wy1)
{
    __shared__ __align__(16) float Ws[16 * 68];
    __shared__ __align__(16) float Xs[16 * 132];
    int p = blockIdx.z, b = blockIdx.y, n0 = blockIdx.x * 128;
    const float* W = (p == 0) ? ws1 : (p == 1) ? wx1 : wy1;
    const float* X = (p == 2) ? (y + (size_t)b * CY * N_) : (x + (size_t)b * CX * N_);
    int K = (p == 2) ? CY : CX;
    float* C = g_z1 + ((size_t)(p * B_ + b) * M_) * N_ + n0;
    int tid = threadIdx.x;
    int ty = tid >> 5, tx = tid & 31;
    u64 acc[4][4];
#pragma unroll
    for (int r = 0; r < 4; ++r) { acc[r][0] = acc[r][1] = acc[r][2] = acc[r][3] = 0ull; }

    for (int k0 = 0; k0 < K; k0 += 16) {
        {
            int m = tid >> 2, kq = tid & 3;
            float4 w4 = *(const float4*)(W + (size_t)m * K + k0 + 4 * kq);
            Ws[(4 * kq + 0) * 68 + m] = w4.x; Ws[(4 * kq + 1) * 68 + m] = w4.y;
            Ws[(4 * kq + 2) * 68 + m] = w4.z; Ws[(4 * kq + 3) * 68 + m] = w4.w;
        }
#pragma unroll
        for (int it = 0; it < 2; ++it) {
            int idx = it * 256 + tid;
            int k = idx >> 5, nq = idx & 31;
            *(float4*)(Xs + k * 132 + 4 * nq) =
                *(const float4*)(X + (size_t)(k0 + k) * N_ + n0 + 4 * nq);
        }
        __syncthreads();
#pragma unroll
        for (int d = 0; d < 16; ++d) {
            ulonglong2 a01 = *(const ulonglong2*)(Ws + d * 68 + 8 * ty);
            ulonglong2 a23 = *(const ulonglong2*)(Ws + d * 68 + 8 * ty + 4);
            float4 bb = *(const float4*)(Xs + d * 132 + 4 * tx);
            u64 b0 = d2(bb.x), b1 = d2(bb.y), b2 = d2(bb.z), b3 = d2(bb.w);
            u64 av[4] = {a01.x, a01.y, a23.x, a23.y};
#pragma unroll
            for (int r = 0; r < 4; ++r) {
                fma2(acc[r][0], av[r], b0); fma2(acc[r][1], av[r], b1);
                fma2(acc[r][2], av[r], b2); fma2(acc[r][3], av[r], b3);
            }
        }
        __syncthreads();
    }
#pragma unroll
    for (int r = 0; r < 4; ++r) {
        float l0, h0, l1, h1, l2, h2, l3, h3;
        up2(acc[r][0], l0, h0); up2(acc[r][1], l1, h1);
        up2(acc[r][2], l2, h2); up2(acc[r][3], l3, h3);
        *(float4*)(C + (size_t)(8 * ty + 2 * r) * N_ + 4 * tx) = make_float4(l0, l1, l2, l3);
        *(float4*)(C + (size_t)(8 * ty + 2 * r + 1) * N_ + 4 * tx) = make_float4(h0, h1, h2, h3);
    }
}

// ---------------- per-channel batch stats -> folded BN affine ----------------
__global__ void k_stats(int which,
                        const float* __restrict__ gs, const float* __restrict__ bs,
                        const float* __restrict__ gx, const float* __restrict__ bx,
                        const float* __restrict__ gy, const float* __restrict__ by)
{
    __shared__ float s1[256], s2[256];
    const float* Z = (which == 0) ? g_z1 : g_z2;
    float* ao = (which == 0) ? g_a1 : g_a2;
    float* bo = (which == 0) ? g_bf1 : g_bf2;
    int ch = blockIdx.x, p = ch >> 6, m = ch & 63;
    int tid = threadIdx.x;
    float sum = 0.f, sq = 0.f;
    const float* base = Z + ((size_t)(p * B_) * M_ + m) * N_;
    for (int b = 0; b < B_; ++b) {
        const float* row = base + (size_t)b * M_ * N_;
        for (int i = tid; i < N_; i += 256) { float v = row[i]; sum += v; sq += v * v; }
    }
    s1[tid] = sum; s2[tid] = sq; __syncthreads();
    for (int off = 128; off; off >>= 1) {
        if (tid < off) { s1[tid] += s1[tid + off]; s2[tid] += s2[tid + off]; }
        __syncthreads();
    }
    if (tid == 0) {
        float mean = s1[0] / TOT_;
        float var = s2[0] / TOT_ - mean * mean;
        const float* g = (p == 0) ? gs : (p == 1) ? gx : gy;
        const float* bb = (p == 0) ? bs : (p == 1) ? bx : by;
        float a = g[m] * rsqrtf(var + EPS_);
        ao[ch] = a;
        bo[ch] = bb[m] - a * mean;
    }
}

// ---------------- fold BN1 into stage-2 weights ----------------
__global__ void k_foldw2(const float* __restrict__ ws2, const float* __restrict__ wx2,
                         const float* __restrict__ wy2)
{
    int p = blockIdx.x, tid = threadIdx.x;
    const float* w2 = (p == 0) ? ws2 : (p == 1) ? wx2 : wy2;
    for (int idx = tid; idx < 4096; idx += 256) {
        int k = idx & 63;
        g_w2eff[p * 4096 + idx] = w2[idx] * g_a1[p * 64 + k];
    }
    if (tid < 64) {
        float s = 0.f;
#pragma unroll 8
        for (int k = 0; k < 64; ++k) s += w2[tid * 64 + k] * g_bf1[p * 64 + k];
        g_c2[p * 64 + tid] = s;
    }
}

// ---------------- stage-2 conv1x1 (K=64), row-pair packed ----------------
__global__ __launch_bounds__(256) void k_gemm2()
{
    __shared__ __align__(16) float Ws[16 * 68];
    __shared__ __align__(16) float Xs[16 * 132];
    int z = blockIdx.y, p = z >> 2;
    int n0 = blockIdx.x * 128;
    const float* W = g_w2eff + p * 4096;
    const float* X = g_z1 + (size_t)z * M_ * N_;
    float* C = g_z2 + (size_t)z * M_ * N_ + n0;
    int tid = threadIdx.x;
    int ty = tid >> 5, tx = tid & 31;
    u64 acc[4][4];
#pragma unroll
    for (int r = 0; r < 4; ++r) { acc[r][0] = acc[r][1] = acc[r][2] = acc[r][3] = 0ull; }

    for (int k0 = 0; k0 < 64; k0 += 16) {
        {
            int m = tid >> 2, kq = tid & 3;
            float4 w4 = *(const float4*)(W + (size_t)m * 64 + k0 + 4 * kq);
            Ws[(4 * kq + 0) * 68 + m] = w4.x; Ws[(4 * kq + 1) * 68 + m] = w4.y;
            Ws[(4 * kq + 2) * 68 + m] = w4.z; Ws[(4 * kq + 3) * 68 + m] = w4.w;
        }
#pragma unroll
        for (int it = 0; it < 2; ++it) {
            int idx = it * 256 + tid;
            int k = idx >> 5, nq = idx & 31;
            *(float4*)(Xs + k * 132 + 4 * nq) =
                *(const float4*)(X + (size_t)(k0 + k) * N_ + n0 + 4 * nq);
        }
        __syncthreads();
#pragma unroll
        for (int d = 0; d < 16; ++d) {
            ulonglong2 a01 = *(const ulonglong2*)(Ws + d * 68 + 8 * ty);
            ulonglong2 a23 = *(const ulonglong2*)(Ws + d * 68 + 8 * ty + 4);
            float4 bb = *(const float4*)(Xs + d * 132 + 4 * tx);
            u64 b0 = d2(bb.x), b1 = d2(bb.y), b2 = d2(bb.z), b3 = d2(bb.w);
            u64 av[4] = {a01.x, a01.y, a23.x, a23.y};
#pragma unroll
            for (int r = 0; r < 4; ++r) {
                fma2(acc[r][0], av[r], b0); fma2(acc[r][1], av[r], b1);
                fma2(acc[r][2], av[r], b2); fma2(acc[r][3], av[r], b3);
            }
        }
        __syncthreads();
    }
#pragma unroll
    for (int r = 0; r < 4; ++r) {
        float l0, h0, l1, h1, l2, h2, l3, h3;
        up2(acc[r][0], l0, h0); up2(acc[r][1], l1, h1);
        up2(acc[r][2], l2, h2); up2(acc[r][3], l3, h3);
        float bl = g_c2[p * 64 + 8 * ty + 2 * r];
        float bh = g_c2[p * 64 + 8 * ty + 2 * r + 1];
        *(float4*)(C + (size_t)(8 * ty + 2 * r) * N_ + 4 * tx) =
            make_float4(l0 + bl, l1 + bl, l2 + bl, l3 + bl);
        *(float4*)(C + (size_t)(8 * ty + 2 * r + 1) * N_ + 4 * tx) =
            make_float4(h0 + bh, h1 + bh, h2 + bh, h3 + bh);
    }
}

// ---------------- fused flash attention: 128 queries/block, 64-key tiles ----------------
// S packed over query-row pairs; O packed over value-column pairs.
__global__ __launch_bounds__(256) void k_attn()
{
    extern __shared__ float sm[];
    float* Qs = sm;                   // 64*132  [m][i]
    float* Ks = Qs + 64 * 132;        // 64*68   [m][j]
    float* Ps = Ks + 64 * 68;         // 128*68  [i][j]
    float* Vs = Ps + 128 * 68;        // 64*68   [j][c] (transposed, 16B-aligned rows)
    int b = blockIdx.y;
    int q0 = blockIdx.x * 128;
    int tid = threadIdx.x;
    int ty = tid >> 4, tx = tid & 15;   // rows 8*ty.., cols 4*tx..

    const float* zq = g_z2 + ((size_t)(1 * B_ + b) * M_) * N_;  // f_x  (queries)
    const float* zk = g_z2 + ((size_t)(2 * B_ + b) * M_) * N_;  // f_y  (keys)
    const float* zv = g_z2 + ((size_t)(0 * B_ + b) * M_) * N_;  // f_self (values)

    // load Q tile (128 rows x 64 m), BN2 applied, stored transposed Qs[m][i]
#pragma unroll
    for (int it = 0; it < 8; ++it) {
        int idx = it * 256 + tid;
        int m = idx >> 5, iq = idx & 31;
        float a = g_a2[64 + m], bet = g_bf2[64 + m];
        float4 v = *(const float4*)(zq + (size_t)m * N_ + q0 + 4 * iq);
        *(float4*)(Qs + m * 132 + 4 * iq) =
            make_float4(a * v.x + bet, a * v.y + bet, a * v.z + bet, a * v.w + bet);
    }

    u64 Oc[8][2];
    float mrow[8], lrow[8];
    const float NEG_INF = __int_as_float(0xff800000);
#pragma unroll
    for (int r = 0; r < 8; ++r) {
        Oc[r][0] = Oc[r][1] = 0ull;
        mrow[r] = NEG_INF; lrow[r] = 0.f;
    }

    for (int j0 = 0; j0 < N_; j0 += 64) {
        __syncthreads();  // protect Ks/Vs from previous PV; makes Qs visible on first iter
        // K tile: Ks[m][j], BN2 applied
#pragma unroll
        for (int it = 0; it < 4; ++it) {
            int idx = it * 256 + tid;
            int m = idx >> 4, jq = idx & 15;
            float a = g_a2[128 + m], bet = g_bf2[128 + m];
            float4 v = *(const float4*)(zk + (size_t)m * N_ + j0 + 4 * jq);
            *(float4*)(Ks + m * 68 + 4 * jq) =
                make_float4(a * v.x + bet, a * v.y + bet, a * v.z + bet, a * v.w + bet);
        }
        // V tile: transposed store Vs[j][c], BN2 applied
#pragma unroll
        for (int it = 0; it < 4; ++it) {
            int idx = it * 256 + tid;
            int c = idx >> 4, jq = idx & 15;
            float a = g_a2[c], bet = g_bf2[c];
            float4 v = *(const float4*)(zv + (size_t)c * N_ + j0 + 4 * jq);
            Vs[(4 * jq + 0) * 68 + c] = a * v.x + bet;
            Vs[(4 * jq + 1) * 68 + c] = a * v.y + bet;
            Vs[(4 * jq + 2) * 68 + c] = a * v.z + bet;
            Vs[(4 * jq + 3) * 68 + c] = a * v.w + bet;
        }
        __syncthreads();

        // S = Q @ K  (contraction over m), row-pair packed
        u64 accS[4][4];
#pragma unroll
        for (int r = 0; r < 4; ++r) { accS[r][0] = accS[r][1] = accS[r][2] = accS[r][3] = 0ull; }
#pragma unroll 8
        for (int d = 0; d < 64; ++d) {
            ulonglong2 a01 = *(const ulonglong2*)(Qs + d * 132 + 8 * ty);
            ulonglong2 a23 = *(const ulonglong2*)(Qs + d * 132 + 8 * ty + 4);
            float4 bb = *(const float4*)(Ks + d * 68 + 4 * tx);
            u64 b0 = d2(bb.x), b1 = d2(bb.y), b2 = d2(bb.z), b3 = d2(bb.w);
            u64 av[4] = {a01.x, a01.y, a23.x, a23.y};
#pragma unroll
            for (int r = 0; r < 4; ++r) {
                fma2(accS[r][0], av[r], b0); fma2(accS[r][1], av[r], b1);
                fma2(accS[r][2], av[r], b2); fma2(accS[r][3], av[r], b3);
            }
        }
        // unpack to per-row scalars
        float s[8][4];
#pragma unroll
        for (int r = 0; r < 4; ++r) {
#pragma unroll
            for (int c = 0; c < 4; ++c) {
                up2(accS[r][c], s[2 * r][c], s[2 * r + 1][c]);
            }
        }

        // online softmax (row groups of 16 threads)
#pragma unroll
        for (int r = 0; r < 8; ++r) {
            float rm = fmaxf(fmaxf(s[r][0], s[r][1]), fmaxf(s[r][2], s[r][3]));
            rm = fmaxf(rm, __shfl_xor_sync(0xffffffffu, rm, 1));
            rm = fmaxf(rm, __shfl_xor_sync(0xffffffffu, rm, 2));
            rm = fmaxf(rm, __shfl_xor_sync(0xffffffffu, rm, 4));
            rm = fmaxf(rm, __shfl_xor_sync(0xffffffffu, rm, 8));
            float mnew = fmaxf(mrow[r], rm);
            float corr = __expf(mrow[r] - mnew);
            mrow[r] = mnew;
            float ps = 0.f;
#pragma unroll
            for (int c = 0; c < 4; ++c) {
                float e = __expf(s[r][c] - mnew);
                s[r][c] = e; ps += e;
            }
            ps += __shfl_xor_sync(0xffffffffu, ps, 1);
            ps += __shfl_xor_sync(0xffffffffu, ps, 2);
            ps += __shfl_xor_sync(0xffffffffu, ps, 4);
            ps += __shfl_xor_sync(0xffffffffu, ps, 8);
            lrow[r] = lrow[r] * corr + ps;
            u64 cd = d2(corr);
            mul2(Oc[r][0], cd); mul2(Oc[r][1], cd);
            *(float4*)(Ps + (8 * ty + r) * 68 + 4 * tx) =
                make_float4(s[r][0], s[r][1], s[r][2], s[r][3]);
        }
        __syncthreads();

        // O += P @ V  (contraction over j), column-pair packed
#pragma unroll 8
        for (int d = 0; d < 64; ++d) {
            ulonglong2 v = *(const ulonglong2*)(Vs + d * 68 + 4 * tx);
#pragma unroll
            for (int r = 0; r < 8; ++r) {
                u64 p = d2(Ps[(8 * ty + r) * 68 + d]);
                fma2(Oc[r][0], p, v.x); fma2(Oc[r][1], p, v.y);
            }
        }
    }

    // normalize + store transposed into g_fout[b][c][n]
#pragma unroll
    for (int r = 0; r < 8; ++r) {
        float inv = 1.f / lrow[r];
        int n = q0 + 8 * ty + r;
        float o0, o1, o2, o3;
        up2(Oc[r][0], o0, o1); up2(Oc[r][1], o2, o3);
        g_fout[((size_t)b * M_ + 4 * tx + 0) * N_ + n] = o0 * inv;
        g_fout[((size_t)b * M_ + 4 * tx + 1) * N_ + n] = o1 * inv;
        g_fout[((size_t)b * M_ + 4 * tx + 2) * N_ + n] = o2 * inv;
        g_fout[((size_t)b * M_ + 4 * tx + 3) * N_ + n] = o3 * inv;
    }
}

// ---------------- gram of fout (for exact final-BN variance) ----------------
__global__ __launch_bounds__(256) void k_gram()
{
    __shared__ float Fs[64 * 129];
    int chunk = blockIdx.x;
    int b = chunk >> 2, nbase = (chunk & 3) * 1024;
    int tid = threadIdx.x;
    int ty = tid >> 4, tx = tid & 15;
    float acc[4][4];
#pragma unroll
    for (int r = 0; r < 4; ++r) { acc[r][0] = acc[r][1] = acc[r][2] = acc[r][3] = 0.f; }

    for (int sub = 0; sub < 8; ++sub) {
        int n0 = nbase + sub * 128;
        __syncthreads();
#pragma unroll
        for (int it = 0; it < 8; ++it) {
            int idx = it * 256 + tid;
            int m = idx >> 5, nq = idx & 31;
            float4 v = *(const float4*)(g_fout + ((size_t)b * M_ + m) * N_ + n0 + 4 * nq);
            Fs[m * 129 + 4 * nq + 0] = v.x; Fs[m * 129 + 4 * nq + 1] = v.y;
            Fs[m * 129 + 4 * nq + 2] = v.z; Fs[m * 129 + 4 * nq + 3] = v.w;
        }
        __syncthreads();
        for (int d = 0; d < 128; ++d) {
            float a0 = Fs[(4 * ty + 0) * 129 + d];
            float a1 = Fs[(4 * ty + 1) * 129 + d];
            float a2 = Fs[(4 * ty + 2) * 129 + d];
            float a3 = Fs[(4 * ty + 3) * 129 + d];
            float b0 = Fs[(4 * tx + 0) * 129 + d];
            float b1 = Fs[(4 * tx + 1) * 129 + d];
            float b2 = Fs[(4 * tx + 2) * 129 + d];
            float b3 = Fs[(4 * tx + 3) * 129 + d];
            acc[0][0] += a0 * b0; acc[0][1] += a0 * b1; acc[0][2] += a0 * b2; acc[0][3] += a0 * b3;
            acc[1][0] += a1 * b0; acc[1][1] += a1 * b1; acc[1][2] += a1 * b2; acc[1][3] += a1 * b3;
            acc[2][0] += a2 * b0; acc[2][1] += a2 * b1; acc[2][2] += a2 * b2; acc[2][3] += a2 * b3;
            acc[3][0] += a3 * b0; acc[3][1] += a3 * b1; acc[3][2] += a3 * b2; acc[3][3] += a3 * b3;
        }
    }
#pragma unroll
    for (int r = 0; r < 4; ++r)
#pragma unroll
        for (int c = 0; c < 4; ++c)
            atomicAdd(&g_gram[(4 * ty + r) * 64 + 4 * tx + c], acc[r][c]);
}

// ---------------- channel sums of fout ----------------
__global__ void k_meanf()
{
    __shared__ float s1[256];
    int m = blockIdx.x, tid = threadIdx.x;
    float sum = 0.f;
    for (int b = 0; b < B_; ++b) {
        const float* row = g_fout + ((size_t)b * M_ + m) * N_;
        for (int i = tid; i < N_; i += 256) sum += row[i];
    }
    s1[tid] = sum; __syncthreads();
    for (int off = 128; off; off >>= 1) {
        if (tid < off) s1[tid] += s1[tid + off];
        __syncthreads();
    }
    if (tid == 0) g_meanf[m] = s1[0];
}

// ---------------- final BN affine via gram ----------------
__global__ void k_bnup(const float* __restrict__ wu, const float* __restrict__ gu,
                       const float* __restrict__ bu)
{
    __shared__ float s1[64], s2[64];
    int c = blockIdx.x, t = threadIdx.x;
    float tmp = 0.f;
    for (int k = 0; k < 64; ++k) tmp += g_gram[t * 64 + k] * wu[c * 64 + k];
    float wt = wu[c * 64 + t];
    s1[t] = wt * tmp;
    s2[t] = wt * g_meanf[t];
    __syncthreads();
    for (int off = 32; off; off >>= 1) {
        if (t < off) { s1[t] += s1[t + off]; s2[t] += s2[t + off]; }
        __syncthreads();
    }
    if (t == 0) {
        float mean = s2[0] / TOT_;
        float eu2 = s1[0] / TOT_;
        float var = eu2 - mean * mean;
        float a = gu[c] * rsqrtf(var + EPS_);
        g_au[c] = a;
        g_bu[c] = bu[c] - a * mean;
    }
}

// ---------------- final: out = x + BN(wu @ fout), row-pair packed ----------------
__global__ __launch_bounds__(256) void k_final(const float* __restrict__ x,
                                               const float* __restrict__ wu,
                                               float* __restrict__ out)
{
    __shared__ __align__(16) float Ws[16 * 68];
    __shared__ __align__(16) float Xs[16 * 132];
    int n0 = blockIdx.x * 128, c0 = blockIdx.y * 64, b = blockIdx.z;
    const float* F = g_fout + (size_t)b * M_ * N_;
    int tid = threadIdx.x;
    int ty = tid >> 5, tx = tid & 31;
    u64 acc[4][4];
#pragma unroll
    for (int r = 0; r < 4; ++r) { acc[r][0] = acc[r][1] = acc[r][2] = acc[r][3] = 0ull; }

    for (int k0 = 0; k0 < 64; k0 += 16) {
        {
            int m = tid >> 2, kq = tid & 3;
            float4 w4 = *(const float4*)(wu + (size_t)(c0 + m) * 64 + k0 + 4 * kq);
            Ws[(4 * kq + 0) * 68 + m] = w4.x; Ws[(4 * kq + 1) * 68 + m] = w4.y;
            Ws[(4 * kq + 2) * 68 + m] = w4.z; Ws[(4 * kq + 3) * 68 + m] = w4.w;
        }
#pragma unroll
        for (int it = 0; it < 2; ++it) {
            int idx = it * 256 + tid;
            int k = idx >> 5, nq = idx & 31;
            *(float4*)(Xs + k * 132 + 4 * nq) =
                *(const float4*)(F + (size_t)(k0 + k) * N_ + n0 + 4 * nq);
        }
        __syncthreads();
#pragma unroll
        for (int d = 0; d < 16; ++d) {
            ulonglong2 a01 = *(const ulonglong2*)(Ws + d * 68 + 8 * ty);
            ulonglong2 a23 = *(const ulonglong2*)(Ws + d * 68 + 8 * ty + 4);
            float4 bb = *(const float4*)(Xs + d * 132 + 4 * tx);
            u64 b0 = d2(bb.x), b1 = d2(bb.y), b2 = d2(bb.z), b3 = d2(bb.w);
            u64 av[4] = {a01.x, a01.y, a23.x, a23.y};
#pragma unroll
            for (int r = 0; r < 4; ++r) {
                fma2(acc[r][0], av[r], b0); fma2(acc[r][1], av[r], b1);
                fma2(acc[r][2], av[r], b2); fma2(acc[r][3], av[r], b3);
            }
        }
        __syncthreads();
    }
#pragma unroll
    for (int r = 0; r < 4; ++r) {
        float l0, h0, l1, h1, l2, h2, l3, h3;
        up2(acc[r][0], l0, h0); up2(acc[r][1], l1, h1);
        up2(acc[r][2], l2, h2); up2(acc[r][3], l3, h3);
        int cl = c0 + 8 * ty + 2 * r;
        int ch = cl + 1;
        float al = g_au[cl], bl = g_bu[cl];
        float ah = g_au[ch], bh = g_bu[ch];
        size_t ol = ((size_t)b * CX + cl) * N_ + n0 + 4 * tx;
        size_t oh = ((size_t)b * CX + ch) * N_ + n0 + 4 * tx;
        float4 xl = *(const float4*)(x + ol);
        float4 xh = *(const float4*)(x + oh);
        *(float4*)(out + ol) = make_float4(
            xl.x + al * l0 + bl, xl.y + al * l1 + bl, xl.z + al * l2 + bl, xl.w + al * l3 + bl);
        *(float4*)(out + oh) = make_float4(
            xh.x + ah * h0 + bh, xh.y + ah * h1 + bh, xh.z + ah * h2 + bh, xh.w + ah * h3 + bh);
    }
}

#define ATTN_SMEM ((64 * 132 + 64 * 68 + 128 * 68 + 64 * 68) * 4)

extern "C" void kernel_launch(void* const* d_in, const int* in_sizes, int n_in,
                              void* d_out, int out_size)
{
    const float* x   = (const float*)d_in[0];
    const float* y   = (const float*)d_in[1];
    const float* ws1 = (const float*)d_in[2];
    const float* gs1 = (const float*)d_in[3];
    const float* bs1 = (const float*)d_in[4];
    const float* ws2 = (const float*)d_in[5];
    const float* gs2 = (const float*)d_in[6];
    const float* bs2 = (const float*)d_in[7];
    const float* wx1 = (const float*)d_in[8];
    const float* gx1 = (const float*)d_in[9];
    const float* bx1 = (const float*)d_in[10];
    const float* wx2 = (const float*)d_in[11];
    const float* gx2 = (const float*)d_in[12];
    const float* bx2 = (const float*)d_in[13];
    const float* wy1 = (const float*)d_in[14];
    const float* gy1 = (const float*)d_in[15];
    const float* by1 = (const float*)d_in[16];
    const float* wy2 = (const float*)d_in[17];
    const float* gy2 = (const float*)d_in[18];
    const float* by2 = (const float*)d_in[19];
    const float* wu  = (const float*)d_in[20];
    const float* gu  = (const float*)d_in[21];
    const float* bu  = (const float*)d_in[22];
    float* out = (float*)d_out;

    cudaFuncSetAttribute(k_attn, cudaFuncAttributeMaxDynamicSharedMemorySize, ATTN_SMEM);

    k_zero<<<1, 256>>>();
    k_gemm1<<<dim3(32, B_, 3), 256>>>(x, y, ws1, wx1, wy1);
    k_stats<<<192, 256>>>(0, gs1, bs1, gx1, bx1, gy1, by1);
    k_foldw2<<<3, 256>>>(ws2, wx2, wy2);
    k_gemm2<<<dim3(32, 12), 256>>>();
    k_stats<<<192, 256>>>(1, gs2, bs2, gx2, bx2, gy2, by2);
    k_attn<<<dim3(32, B_), 256, ATTN_SMEM>>>();
    k_gram<<<16, 256>>>();
    k_meanf<<<64, 256>>>();
    k_bnup<<<512, 64>>>(wu, gu, bu);
    k_final<<<dim3(32, 8, B_), 256>>>(x, wu, out);
}